// round 9
// baseline (speedup 1.0000x reference)
#include <cuda_runtime.h>
#include <math.h>

#define BS 8
#define CC 256
#define NN 1500
#define HH 8
#define DK 32

// ---------------- scratch (static device globals; no allocs) ----------------
// q/k/v stored head-interleaved: [b][n][h*DK]  (256 floats per token row)
__device__ float g_q[(size_t)BS * NN * CC];
__device__ float g_k[(size_t)BS * NN * CC];
__device__ float g_v[(size_t)BS * NN * CC];
__device__ float g_val[(size_t)BS * NN * CC];              // [b][n][c]
__device__ unsigned short g_nbr[(size_t)BS * NN * NN];     // per-row neighbor j lists
__device__ int g_cnt[BS * NN];
__device__ int g_perm[BS * NN];                            // spatial-sorted order

// ---------------- tf32 helpers ----------------------------------------------
__device__ __forceinline__ unsigned tf32_bits(float x) {
    unsigned u;
    asm("cvt.rna.tf32.f32 %0, %1;" : "=r"(u) : "f"(x));
    return u;
}
__device__ __forceinline__ void mma_tf32(float* c, const unsigned* a,
                                         const unsigned* b) {
    asm volatile(
        "mma.sync.aligned.m16n8k8.row.col.f32.tf32.tf32.f32 "
        "{%0,%1,%2,%3}, {%4,%5,%6,%7}, {%8,%9}, {%0,%1,%2,%3};"
        : "+f"(c[0]), "+f"(c[1]), "+f"(c[2]), "+f"(c[3])
        : "r"(a[0]), "r"(a[1]), "r"(a[2]), "r"(a[3]), "r"(b[0]), "r"(b[1]));
}

// ---------------- fused prep: sort (8) + mask (1504) + qkv (1152) -----------
#define SORT_BLKS 8
#define MASK_BLKS (188 * BS)
#define QKV_BLKS  (6 * BS * HH * 3)

__global__ __launch_bounds__(256) void prep_kernel(const float* __restrict__ boxes,
                                                   const float* __restrict__ cm,
                                                   const float* __restrict__ qin,
                                                   const float* __restrict__ kin,
                                                   const float* __restrict__ vin,
                                                   const float* __restrict__ wq,
                                                   const float* __restrict__ wk,
                                                   const float* __restrict__ wv) {
    __shared__ __align__(16) char sbuf[NN * 24];   // 36000 B union
    int blk = blockIdx.x;
    int t = threadIdx.x;

    if (blk < SORT_BLKS) {
        // ----- spatial counting sort, one block per batch -----
        int* hist = (int*)sbuf;
        int* offs = hist + 64;
        int b = blk;
        if (t < 64) hist[t] = 0;
        __syncthreads();
        const float4* bb = (const float4*)(boxes + (size_t)b * NN * 4);
        for (int n = t; n < NN; n += 256) {
            float4 bx = bb[n];
            int kx = min(7, max(0, (int)(bx.x * 8.0f)));
            int ky = min(7, max(0, (int)(bx.y * 8.0f)));
            atomicAdd(&hist[kx * 8 + ky], 1);
        }
        __syncthreads();
        if (t == 0) {
            int run = 0;
            for (int k = 0; k < 64; k++) { offs[k] = run; run += hist[k]; }
        }
        __syncthreads();
        for (int n = t; n < NN; n += 256) {
            float4 bx = bb[n];
            int kx = min(7, max(0, (int)(bx.x * 8.0f)));
            int ky = min(7, max(0, (int)(bx.y * 8.0f)));
            int pos = atomicAdd(&offs[kx * 8 + ky], 1);
            g_perm[b * NN + pos] = n;
        }
        return;
    }

    if (blk < SORT_BLKS + MASK_BLKS) {
        // ----- mask + neighbor list, warp per query (packed smem) -----
        int u = blk - SORT_BLKS;
        int b = u / 188;
        int bx = u % 188;
        float4* sbox = (float4*)sbuf;              // (x1, y1, x2, y2)
        float2* sac = (float2*)(sbuf + NN * 16);   // (area, cm)
        const float4* bb = (const float4*)(boxes + (size_t)b * NN * 4);
        for (int idx = t; idx < NN; idx += 256) {
            float4 bxv = bb[idx];
            float x1 = bxv.x - 0.5f * bxv.z;
            float x2 = bxv.x + 0.5f * bxv.z;
            float y1 = bxv.y - 0.5f * bxv.w;
            float y2 = bxv.y + 0.5f * bxv.w;
            sbox[idx] = make_float4(x1, y1, x2, y2);
            sac[idx] = make_float2((x2 - x1) * (y2 - y1),
                                   cm[(size_t)b * NN + idx]);
        }
        __syncthreads();

        int warp = t >> 5, lane = t & 31;
        int i = bx * 8 + warp;
        if (i >= NN) return;
        float4 bi = sbox[i];
        float2 aci = sac[i];
        unsigned short* out = g_nbr + ((size_t)b * NN + i) * NN;
        int cnt = 0;
        for (int jb = 0; jb < NN; jb += 32) {
            int j = jb + lane;
            bool nbq = false;
            if (j < NN) {
                float4 bj = sbox[j];
                float2 acj = sac[j];
                float ltx = fmaxf(bi.x, bj.x);
                float lty = fmaxf(bi.y, bj.y);
                float rbx = fminf(bi.z, bj.z);
                float rby = fminf(bi.w, bj.w);
                float iw = fmaxf(rbx - ltx, 0.0f);
                float ih = fmaxf(rby - lty, 0.0f);
                float inter = iw * ih;
                float uni = (aci.x + acj.x) - inter;
                float prod = aci.y * acj.y;
                if (prod == 1.0f) {
                    // exact predicate for fl_RN(inter/uni) > 0.5, no divide
                    float i2 = inter + inter;
                    if (i2 > uni * 1.00001f) nbq = true;
                    else if (i2 < uni * 0.99999f) nbq = false;
                    else nbq = ((double)inter >
                                (double)uni * 0.5000000298023223876953125);
                } else {
                    float iou = __fdiv_rn(inter, uni);
                    nbq = (iou * prod) > 0.5f;
                }
            }
            unsigned bal = __ballot_sync(0xffffffffu, nbq);
            int pos = cnt + __popc(bal & ((1u << lane) - 1u));
            if (nbq) out[pos] = (unsigned short)j;
            cnt += __popc(bal);
        }
        if (lane == 0) g_cnt[b * NN + i] = cnt;
        return;
    }

    // ----- qkv head projections -----
    {
        int u = blk - SORT_BLKS - MASK_BLKS;       // [0, 1152)
        int mat = u / (6 * BS * HH);
        int r = u % (6 * BS * HH);
        int bh = r / 6;
        int xc = r % 6;
        int b = bh >> 3, h = bh & 7;
        float4* sw = (float4*)sbuf;                 // 32x32 weights
        const float* W = (mat == 0 ? wq : (mat == 1 ? wk : wv)) + h * DK * DK;
        const float* X = (mat == 0 ? qin : (mat == 1 ? kin : vin));
        float* O = (mat == 0 ? g_q : (mat == 1 ? g_k : g_v));
        sw[t] = ((const float4*)W)[t];
        __syncthreads();

        int i = xc * 256 + t;
        if (i >= NN) return;
        float x[DK];
        const float* xp = X + ((size_t)b * CC + h * DK) * NN + i;
#pragma unroll
        for (int j = 0; j < DK; j++) x[j] = xp[(size_t)j * NN];

        float out[DK];
#pragma unroll
        for (int d = 0; d < DK; d++) {
            float acc = 0.0f;
#pragma unroll
            for (int jq = 0; jq < 8; jq++) {
                float4 w4 = sw[d * 8 + jq];
                acc = fmaf(w4.x, x[jq * 4 + 0], acc);
                acc = fmaf(w4.y, x[jq * 4 + 1], acc);
                acc = fmaf(w4.z, x[jq * 4 + 2], acc);
                acc = fmaf(w4.w, x[jq * 4 + 3], acc);
            }
            out[d] = acc;
        }
        float4* op = (float4*)(O + ((size_t)b * NN + i) * CC + h * DK);
#pragma unroll
        for (int rr = 0; rr < 8; rr++)
            op[rr] = make_float4(out[rr * 4], out[rr * 4 + 1],
                                 out[rr * 4 + 2], out[rr * 4 + 3]);
    }
}

// ---------------- sparse masked attention (warp per query, ALL heads) -------
__device__ __forceinline__ void os_update(float& m, float& l, float4& o,
                                          float s, const float4& v) {
    float mn = fmaxf(m, s);
    float sc = __expf(m - mn);
    float p = __expf(s - mn);        // s==-inf (padding) -> p=0
    l = l * sc + p;
    o.x = fmaf(p, v.x, o.x * sc);
    o.y = fmaf(p, v.y, o.y * sc);
    o.z = fmaf(p, v.z, o.z * sc);
    o.w = fmaf(p, v.w, o.w * sc);
    m = mn;
}

__global__ __launch_bounds__(256, 3) void attn_kernel() {
    int warp = threadIdx.x >> 5, lane = threadIdx.x & 31;
    int gs = blockIdx.x * 8 + warp;          // sorted rank within b*NN
    if (gs >= BS * NN) return;
    int b = gs / NN;
    int gi = b * NN + g_perm[gs];            // actual b*NN + i

    int cnt = g_cnt[gi];
    size_t rowq = (size_t)gi * CC;
    int lo = 4 * lane, hi = 128 + 4 * lane;
    const float* kbase = g_k + (size_t)b * NN * CC;
    const float* vbase = g_v + (size_t)b * NN * CC;
    float* valr = g_val + rowq;

    if (cnt == 0) {   // has_nb == 0 fallback: val = v
        const float* vr = g_v + rowq;
        *(float4*)(valr + lo) = *(const float4*)(vr + lo);
        *(float4*)(valr + hi) = *(const float4*)(vr + hi);
        return;
    }

    float4 q0 = *(const float4*)(g_q + rowq + lo);
    float4 q1 = *(const float4*)(g_q + rowq + hi);
    const unsigned short* nb = g_nbr + (size_t)gi * NN;
    int cm1 = cnt - 1;

    float minit = (cnt < NN) ? 0.0f : -INFINITY;
    float m0 = minit, m1 = minit, l0 = 0.f, l1 = 0.f;
    float4 o0 = {0,0,0,0}, o1 = {0,0,0,0};

#define R8(s) s += __shfl_xor_sync(0xffffffffu, s, 1); \
              s += __shfl_xor_sync(0xffffffffu, s, 2); \
              s += __shfl_xor_sync(0xffffffffu, s, 4);

    for (int t = 0; t < cnt; t += 2) {
        int jA = nb[t], jB = nb[min(t + 1, cm1)];
        const float* kA = kbase + (size_t)jA * CC;
        const float* vA = vbase + (size_t)jA * CC;
        const float* kB = kbase + (size_t)jB * CC;
        const float* vB = vbase + (size_t)jB * CC;
        float4 kA0 = *(const float4*)(kA + lo), kA1 = *(const float4*)(kA + hi);
        float4 vA0 = *(const float4*)(vA + lo), vA1 = *(const float4*)(vA + hi);
        float4 kB0 = *(const float4*)(kB + lo), kB1 = *(const float4*)(kB + hi);
        float4 vB0 = *(const float4*)(vB + lo), vB1 = *(const float4*)(vB + hi);

        float sA0 = q0.x * kA0.x + q0.y * kA0.y + q0.z * kA0.z + q0.w * kA0.w;
        float sA1 = q1.x * kA1.x + q1.y * kA1.y + q1.z * kA1.z + q1.w * kA1.w;
        float sB0 = q0.x * kB0.x + q0.y * kB0.y + q0.z * kB0.z + q0.w * kB0.w;
        float sB1 = q1.x * kB1.x + q1.y * kB1.y + q1.z * kB1.z + q1.w * kB1.w;
        R8(sA0) R8(sA1) R8(sB0) R8(sB1)
        if (t + 1 >= cnt) { sB0 = -INFINITY; sB1 = -INFINITY; }

        os_update(m0, l0, o0, sA0, vA0);
        os_update(m0, l0, o0, sB0, vB0);
        os_update(m1, l1, o1, sA1, vA1);
        os_update(m1, l1, o1, sB1, vB1);
    }
#undef R8

    float inv0 = 1.0f / (l0 + 1e-8f);
    float inv1 = 1.0f / (l1 + 1e-8f);
    *(float4*)(valr + lo) = make_float4(o0.x * inv0, o0.y * inv0,
                                        o0.z * inv0, o0.w * inv0);
    *(float4*)(valr + hi) = make_float4(o1.x * inv1, o1.y * inv1,
                                        o1.z * inv1, o1.w * inv1);
}

// ---------------- output projection via 3xTF32 tensor-core MMA --------------
// out[b][co][i] = Wp[co][:] . val[b][i][:] + bias[co]
// Block 256 thr = 8 warps (2 co-halves x 4 i-quarters); tile 128co x 128i;
// K chunk 16. Each operand split x = hi + lo (tf32); acc accumulates
// Alo*Bhi + Ahi*Blo + Ahi*Bhi  -> ~1e-7 relative error (fp32-grade).
#define TCO 128
#define TIT 128
#define TKC 16
__global__ __launch_bounds__(256) void proj_kernel(const float* __restrict__ wp,
                                                   const float* __restrict__ bp,
                                                   float* __restrict__ out) {
    __shared__ float2 As2[TKC][TCO + 1];   // [k][m] = (hi, lo)
    __shared__ float2 Bs2[TKC][TIT + 1];   // [k][n] = (hi, lo)
    int bi = blockIdx.z;
    int coT = blockIdx.y * TCO;
    int iT = blockIdx.x * TIT;
    int t = threadIdx.x;
    int warp = t >> 5, lane = t & 31;
    int wc = warp >> 2;                 // co half (0/1) -> +64
    int wi = warp & 3;                  // i quarter -> +32 each
    int g = lane >> 2;                  // group id 0..7
    int t4 = lane & 3;                  // thread in group 0..3

    int fr = t >> 1;                    // fill row 0..127
    int k0 = (t & 1) * 8;               // fill k-half

    float acc[4][4][4];
#pragma unroll
    for (int a = 0; a < 4; a++)
#pragma unroll
        for (int e = 0; e < 4; e++)
#pragma unroll
            for (int q = 0; q < 4; q++) acc[a][e][q] = 0.0f;

    for (int kc = 0; kc < CC; kc += TKC) {
        // fill A (Wp rows) and B (val rows, transposed) with hi/lo split
#pragma unroll
        for (int hq = 0; hq < 2; hq++) {
            float4 w = *(const float4*)&wp[(size_t)(coT + fr) * CC + kc + k0 + hq * 4];
            float xs[4] = {w.x, w.y, w.z, w.w};
#pragma unroll
            for (int jj = 0; jj < 4; jj++) {
                unsigned hb = tf32_bits(xs[jj]);
                float hf = __uint_as_float(hb);
                unsigned lb = tf32_bits(xs[jj] - hf);
                As2[k0 + hq * 4 + jj][fr] = make_float2(hf, __uint_as_float(lb));
            }
        }
        {
            int gi = iT + fr;
            float4 v = (gi < NN)
                ? *(const float4*)&g_val[((size_t)bi * NN + gi) * CC + kc + k0]
                : make_float4(0.f, 0.f, 0.f, 0.f);
            float4 v2 = (gi < NN)
                ? *(const float4*)&g_val[((size_t)bi * NN + gi) * CC + kc + k0 + 4]
                : make_float4(0.f, 0.f, 0.f, 0.f);
            float xs[8] = {v.x, v.y, v.z, v.w, v2.x, v2.y, v2.z, v2.w};
#pragma unroll
            for (int jj = 0; jj < 8; jj++) {
                unsigned hb = tf32_bits(xs[jj]);
                float hf = __uint_as_float(hb);
                unsigned lb = tf32_bits(xs[jj] - hf);
                Bs2[k0 + jj][fr] = make_float2(hf, __uint_as_float(lb));
            }
        }
        __syncthreads();

#pragma unroll
        for (int ks = 0; ks < 2; ks++) {
            int kb = ks * 8;
            unsigned bhi[4][2], blo[4][2];
#pragma unroll
            for (int na = 0; na < 4; na++) {
                int n = wi * 32 + na * 8 + g;
                float2 b0 = Bs2[kb + t4][n];
                float2 b1 = Bs2[kb + t4 + 4][n];
                bhi[na][0] = __float_as_uint(b0.x);
                blo[na][0] = __float_as_uint(b0.y);
                bhi[na][1] = __float_as_uint(b1.x);
                blo[na][1] = __float_as_uint(b1.y);
            }
#pragma unroll
            for (int ma = 0; ma < 4; ma++) {
                int m0 = wc * 64 + ma * 16 + g;
                float2 a0 = As2[kb + t4][m0];
                float2 a1 = As2[kb + t4][m0 + 8];
                float2 a2 = As2[kb + t4 + 4][m0];
                float2 a3 = As2[kb + t4 + 4][m0 + 8];
                unsigned ahi[4] = {__float_as_uint(a0.x), __float_as_uint(a1.x),
                                   __float_as_uint(a2.x), __float_as_uint(a3.x)};
                unsigned alo[4] = {__float_as_uint(a0.y), __float_as_uint(a1.y),
                                   __float_as_uint(a2.y), __float_as_uint(a3.y)};
#pragma unroll
                for (int na = 0; na < 4; na++) {
                    mma_tf32(acc[ma][na], alo, bhi[na]);
                    mma_tf32(acc[ma][na], ahi, blo[na]);
                    mma_tf32(acc[ma][na], ahi, bhi[na]);
                }
            }
        }
        __syncthreads();
    }

    // epilogue: c0:(g,2t), c1:(g,2t+1), c2:(g+8,2t), c3:(g+8,2t+1)
#pragma unroll
    for (int ma = 0; ma < 4; ma++) {
        int co0 = coT + wc * 64 + ma * 16 + g;
        float bz0 = bp[co0], bz1 = bp[co0 + 8];
#pragma unroll
        for (int na = 0; na < 4; na++) {
            int i0 = iT + wi * 32 + na * 8 + 2 * t4;
            if (i0 < NN) {   // i0 even, NN even -> pair valid
                *(float2*)&out[((size_t)bi * CC + co0) * NN + i0] =
                    make_float2(acc[ma][na][0] + bz0, acc[ma][na][1] + bz0);
                *(float2*)&out[((size_t)bi * CC + co0 + 8) * NN + i0] =
                    make_float2(acc[ma][na][2] + bz1, acc[ma][na][3] + bz1);
            }
        }
    }
}

// ---------------- launch ----------------------------------------------------
extern "C" void kernel_launch(void* const* d_in, const int* in_sizes, int n_in,
                              void* d_out, int out_size) {
    const float* queries = (const float*)d_in[0];
    const float* keys    = (const float*)d_in[1];
    const float* values  = (const float*)d_in[2];
    const float* boxes   = (const float*)d_in[3];
    const float* curmask = (const float*)d_in[4];
    const float* wq      = (const float*)d_in[5];
    const float* wk      = (const float*)d_in[6];
    const float* wv      = (const float*)d_in[7];
    const float* w_proj  = (const float*)d_in[8];
    const float* b_proj  = (const float*)d_in[9];
    float* out = (float*)d_out;

    prep_kernel<<<SORT_BLKS + MASK_BLKS + QKV_BLKS, 256>>>(
        boxes, curmask, queries, keys, values, wq, wk, wv);
    attn_kernel<<<dim3((BS * NN + 7) / 8), 256>>>();
    proj_kernel<<<dim3((NN + TIT - 1) / TIT, CC / TCO, BS), 256>>>(w_proj, b_proj, out);
}

// round 10
// speedup vs baseline: 1.0063x; 1.0063x over previous
#include <cuda_runtime.h>
#include <math.h>

#define BS 8
#define CC 256
#define NN 1500
#define HH 8
#define DK 32

// ---------------- scratch (static device globals; no allocs) ----------------
// q/k/v stored head-interleaved: [b][n][h*DK]  (256 floats per token row)
__device__ float g_q[(size_t)BS * NN * CC];
__device__ float g_k[(size_t)BS * NN * CC];
__device__ float g_v[(size_t)BS * NN * CC];
__device__ float g_val[(size_t)BS * NN * CC];              // [b][n][c]
__device__ unsigned short g_nbr[(size_t)BS * NN * NN];     // per-row neighbor j lists
__device__ int g_cnt[BS * NN];
__device__ int g_perm[BS * NN];                            // spatial-sorted order

// ---------------- tf32 helpers ----------------------------------------------
__device__ __forceinline__ unsigned tf32_bits(float x) {
    unsigned u;
    asm("cvt.rna.tf32.f32 %0, %1;" : "=r"(u) : "f"(x));
    return u;
}
__device__ __forceinline__ void mma_tf32(float* c, const unsigned* a,
                                         const unsigned* b) {
    asm volatile(
        "mma.sync.aligned.m16n8k8.row.col.f32.tf32.tf32.f32 "
        "{%0,%1,%2,%3}, {%4,%5,%6,%7}, {%8,%9}, {%0,%1,%2,%3};"
        : "+f"(c[0]), "+f"(c[1]), "+f"(c[2]), "+f"(c[3])
        : "r"(a[0]), "r"(a[1]), "r"(a[2]), "r"(a[3]), "r"(b[0]), "r"(b[1]));
}

// ---------------- fused prep: sort (8) + mask (1504) + qkv (1128) -----------
#define SORT_BLKS 8
#define MASK_BLKS (188 * BS)
#define NGRP 47
#define QKV_BLKS (3 * BS * NGRP)

__global__ __launch_bounds__(256) void prep_kernel(const float* __restrict__ boxes,
                                                   const float* __restrict__ cm,
                                                   const float* __restrict__ qin,
                                                   const float* __restrict__ kin,
                                                   const float* __restrict__ vin,
                                                   const float* __restrict__ wq,
                                                   const float* __restrict__ wk,
                                                   const float* __restrict__ wv) {
    __shared__ __align__(16) char sbuf[NN * 24];   // 36000 B union
    int blk = blockIdx.x;
    int t = threadIdx.x;

    if (blk < SORT_BLKS) {
        // ----- spatial counting sort, one block per batch -----
        int* hist = (int*)sbuf;
        int* offs = hist + 64;
        int b = blk;
        if (t < 64) hist[t] = 0;
        __syncthreads();
        const float4* bb = (const float4*)(boxes + (size_t)b * NN * 4);
        for (int n = t; n < NN; n += 256) {
            float4 bx = bb[n];
            int kx = min(7, max(0, (int)(bx.x * 8.0f)));
            int ky = min(7, max(0, (int)(bx.y * 8.0f)));
            atomicAdd(&hist[kx * 8 + ky], 1);
        }
        __syncthreads();
        if (t == 0) {
            int run = 0;
            for (int k = 0; k < 64; k++) { offs[k] = run; run += hist[k]; }
        }
        __syncthreads();
        for (int n = t; n < NN; n += 256) {
            float4 bx = bb[n];
            int kx = min(7, max(0, (int)(bx.x * 8.0f)));
            int ky = min(7, max(0, (int)(bx.y * 8.0f)));
            int pos = atomicAdd(&offs[kx * 8 + ky], 1);
            g_perm[b * NN + pos] = n;
        }
        return;
    }

    if (blk < SORT_BLKS + MASK_BLKS) {
        // ----- mask + neighbor list, warp per query (packed smem) -----
        int u = blk - SORT_BLKS;
        int b = u / 188;
        int bx = u % 188;
        float4* sbox = (float4*)sbuf;              // (x1, y1, x2, y2)
        float2* sac = (float2*)(sbuf + NN * 16);   // (area, cm)
        const float4* bb = (const float4*)(boxes + (size_t)b * NN * 4);
        for (int idx = t; idx < NN; idx += 256) {
            float4 bxv = bb[idx];
            float x1 = bxv.x - 0.5f * bxv.z;
            float x2 = bxv.x + 0.5f * bxv.z;
            float y1 = bxv.y - 0.5f * bxv.w;
            float y2 = bxv.y + 0.5f * bxv.w;
            sbox[idx] = make_float4(x1, y1, x2, y2);
            sac[idx] = make_float2((x2 - x1) * (y2 - y1),
                                   cm[(size_t)b * NN + idx]);
        }
        __syncthreads();

        int warp = t >> 5, lane = t & 31;
        int i = bx * 8 + warp;
        if (i >= NN) return;
        float4 bi = sbox[i];
        float2 aci = sac[i];
        unsigned short* out = g_nbr + ((size_t)b * NN + i) * NN;
        int cnt = 0;
        for (int jb = 0; jb < NN; jb += 32) {
            int j = jb + lane;
            bool nbq = false;
            if (j < NN) {
                float4 bj = sbox[j];
                float2 acj = sac[j];
                float ltx = fmaxf(bi.x, bj.x);
                float lty = fmaxf(bi.y, bj.y);
                float rbx = fminf(bi.z, bj.z);
                float rby = fminf(bi.w, bj.w);
                float iw = fmaxf(rbx - ltx, 0.0f);
                float ih = fmaxf(rby - lty, 0.0f);
                float inter = iw * ih;
                float uni = (aci.x + acj.x) - inter;
                float prod = aci.y * acj.y;
                if (prod == 1.0f) {
                    // exact predicate for fl_RN(inter/uni) > 0.5, no divide
                    float i2 = inter + inter;
                    if (i2 > uni * 1.00001f) nbq = true;
                    else if (i2 < uni * 0.99999f) nbq = false;
                    else nbq = ((double)inter >
                                (double)uni * 0.5000000298023223876953125);
                } else {
                    float iou = __fdiv_rn(inter, uni);
                    nbq = (iou * prod) > 0.5f;
                }
            }
            unsigned bal = __ballot_sync(0xffffffffu, nbq);
            int pos = cnt + __popc(bal & ((1u << lane) - 1u));
            if (nbq) out[pos] = (unsigned short)j;
            cnt += __popc(bal);
        }
        if (lane == 0) g_cnt[b * NN + i] = cnt;
        return;
    }

    // ----- qkv head projections: block = (mat, b, 32-token group) -----
    // warp = head, lane = token. Outputs transposed through smem so global
    // stores are fully-coalesced 1KB rows.
    {
        int u = blk - SORT_BLKS - MASK_BLKS;       // [0, QKV_BLKS)
        int mat = u / (BS * NGRP);
        int r = u % (BS * NGRP);
        int b = r / NGRP;
        int grp = r % NGRP;
        int tok0 = grp * 32;
        int warp = t >> 5, lane = t & 31;

        const float* Wg = (mat == 0 ? wq : (mat == 1 ? wk : wv));
        const float* X = (mat == 0 ? qin : (mat == 1 ? kin : vin));
        float* O = (mat == 0 ? g_q : (mat == 1 ? g_k : g_v));

        // phase 1: all 8 heads' weights -> smem (32 KB)
        float4* sw = (float4*)sbuf;                 // [8*256]
#pragma unroll
        for (int p = 0; p < 8; p++)
            sw[t + p * 256] = ((const float4*)Wg)[t + p * 256];
        __syncthreads();

        // phase 2: compute 32-dim output for (token=lane+tok0, head=warp)
        int i = tok0 + lane;
        bool valid = i < NN;
        float x[DK];
        const float* xp = X + ((size_t)b * CC + warp * DK) * NN + i;
#pragma unroll
        for (int j = 0; j < DK; j++) x[j] = valid ? xp[(size_t)j * NN] : 0.0f;

        const float4* wh = sw + warp * 256;
        float outv[DK];
#pragma unroll
        for (int d = 0; d < DK; d++) {
            float acc = 0.0f;
#pragma unroll
            for (int jq = 0; jq < 8; jq++) {
                float4 w4 = wh[d * 8 + jq];
                acc = fmaf(w4.x, x[jq * 4 + 0], acc);
                acc = fmaf(w4.y, x[jq * 4 + 1], acc);
                acc = fmaf(w4.z, x[jq * 4 + 2], acc);
                acc = fmaf(w4.w, x[jq * 4 + 3], acc);
            }
            outv[d] = acc;
        }
        __syncthreads();   // weights fully read; reuse sbuf as staging

        // phase 3: transpose via smem: stg[c][tok], stride 33 (conflict-free)
        float* stg = (float*)sbuf;                  // [256][33] floats
#pragma unroll
        for (int d = 0; d < DK; d++)
            stg[(warp * DK + d) * 33 + lane] = outv[d];
        __syncthreads();

        // phase 4: coalesced row stores: warp writes 4 token rows
#pragma unroll
        for (int rr = 0; rr < 4; rr++) {
            int n = warp * 4 + rr;
            int gi = tok0 + n;
            if (gi < NN) {
                float f[8];
#pragma unroll
                for (int jj = 0; jj < 8; jj++)
                    f[jj] = stg[(8 * lane + jj) * 33 + n];
                float* orow = O + ((size_t)b * NN + gi) * CC + 8 * lane;
                *(float4*)orow = make_float4(f[0], f[1], f[2], f[3]);
                *(float4*)(orow + 4) = make_float4(f[4], f[5], f[6], f[7]);
            }
        }
    }
}

// ---------------- sparse masked attention (warp per query, ALL heads) -------
__device__ __forceinline__ void os_update(float& m, float& l, float4& o,
                                          float s, const float4& v) {
    float mn = fmaxf(m, s);
    float sc = __expf(m - mn);
    float p = __expf(s - mn);        // s==-inf (padding) -> p=0
    l = l * sc + p;
    o.x = fmaf(p, v.x, o.x * sc);
    o.y = fmaf(p, v.y, o.y * sc);
    o.z = fmaf(p, v.z, o.z * sc);
    o.w = fmaf(p, v.w, o.w * sc);
    m = mn;
}

__global__ __launch_bounds__(256, 3) void attn_kernel() {
    int warp = threadIdx.x >> 5, lane = threadIdx.x & 31;
    int gs = blockIdx.x * 8 + warp;          // sorted rank within b*NN
    if (gs >= BS * NN) return;
    int b = gs / NN;
    int gi = b * NN + g_perm[gs];            // actual b*NN + i

    int cnt = g_cnt[gi];
    size_t rowq = (size_t)gi * CC;
    int lo = 4 * lane, hi = 128 + 4 * lane;
    const float* kbase = g_k + (size_t)b * NN * CC;
    const float* vbase = g_v + (size_t)b * NN * CC;
    float* valr = g_val + rowq;

    if (cnt == 0) {   // has_nb == 0 fallback: val = v
        const float* vr = g_v + rowq;
        *(float4*)(valr + lo) = *(const float4*)(vr + lo);
        *(float4*)(valr + hi) = *(const float4*)(vr + hi);
        return;
    }

    float4 q0 = *(const float4*)(g_q + rowq + lo);
    float4 q1 = *(const float4*)(g_q + rowq + hi);
    const unsigned short* nb = g_nbr + (size_t)gi * NN;
    int cm1 = cnt - 1;

    float minit = (cnt < NN) ? 0.0f : -INFINITY;
    float m0 = minit, m1 = minit, l0 = 0.f, l1 = 0.f;
    float4 o0 = {0,0,0,0}, o1 = {0,0,0,0};

#define R8(s) s += __shfl_xor_sync(0xffffffffu, s, 1); \
              s += __shfl_xor_sync(0xffffffffu, s, 2); \
              s += __shfl_xor_sync(0xffffffffu, s, 4);

    for (int t = 0; t < cnt; t += 2) {
        int jA = nb[t], jB = nb[min(t + 1, cm1)];
        const float* kA = kbase + (size_t)jA * CC;
        const float* vA = vbase + (size_t)jA * CC;
        const float* kB = kbase + (size_t)jB * CC;
        const float* vB = vbase + (size_t)jB * CC;
        float4 kA0 = *(const float4*)(kA + lo), kA1 = *(const float4*)(kA + hi);
        float4 vA0 = *(const float4*)(vA + lo), vA1 = *(const float4*)(vA + hi);
        float4 kB0 = *(const float4*)(kB + lo), kB1 = *(const float4*)(kB + hi);
        float4 vB0 = *(const float4*)(vB + lo), vB1 = *(const float4*)(vB + hi);

        float sA0 = q0.x * kA0.x + q0.y * kA0.y + q0.z * kA0.z + q0.w * kA0.w;
        float sA1 = q1.x * kA1.x + q1.y * kA1.y + q1.z * kA1.z + q1.w * kA1.w;
        float sB0 = q0.x * kB0.x + q0.y * kB0.y + q0.z * kB0.z + q0.w * kB0.w;
        float sB1 = q1.x * kB1.x + q1.y * kB1.y + q1.z * kB1.z + q1.w * kB1.w;
        R8(sA0) R8(sA1) R8(sB0) R8(sB1)
        if (t + 1 >= cnt) { sB0 = -INFINITY; sB1 = -INFINITY; }

        os_update(m0, l0, o0, sA0, vA0);
        os_update(m0, l0, o0, sB0, vB0);
        os_update(m1, l1, o1, sA1, vA1);
        os_update(m1, l1, o1, sB1, vB1);
    }
#undef R8

    float inv0 = 1.0f / (l0 + 1e-8f);
    float inv1 = 1.0f / (l1 + 1e-8f);
    *(float4*)(valr + lo) = make_float4(o0.x * inv0, o0.y * inv0,
                                        o0.z * inv0, o0.w * inv0);
    *(float4*)(valr + hi) = make_float4(o1.x * inv1, o1.y * inv1,
                                        o1.z * inv1, o1.w * inv1);
}

// ---------------- output projection via 3xTF32 tensor-core MMA --------------
// Rows padded to 132 float2 (= 4 mod 16 in 8B banks): fragment LDS.64 banks
// become 4*t4 + g -> all 16 half-warp lanes distinct -> conflict-free.
#define TCO 128
#define TIT 128
#define TKC 16
__global__ __launch_bounds__(256) void proj_kernel(const float* __restrict__ wp,
                                                   const float* __restrict__ bp,
                                                   float* __restrict__ out) {
    __shared__ float2 As2[TKC][TCO + 4];   // [k][m] = (hi, lo)
    __shared__ float2 Bs2[TKC][TIT + 4];   // [k][n] = (hi, lo)
    int bi = blockIdx.z;
    int coT = blockIdx.y * TCO;
    int iT = blockIdx.x * TIT;
    int t = threadIdx.x;
    int warp = t >> 5, lane = t & 31;
    int wc = warp >> 2;                 // co half (0/1) -> +64
    int wi = warp & 3;                  // i quarter -> +32 each
    int g = lane >> 2;                  // group id 0..7
    int t4 = lane & 3;                  // thread in group 0..3

    int fr = t >> 1;                    // fill row 0..127
    int k0 = (t & 1) * 8;               // fill k-half

    float acc[4][4][4];
#pragma unroll
    for (int a = 0; a < 4; a++)
#pragma unroll
        for (int e = 0; e < 4; e++)
#pragma unroll
            for (int q = 0; q < 4; q++) acc[a][e][q] = 0.0f;

    for (int kc = 0; kc < CC; kc += TKC) {
        // fill A (Wp rows) and B (val rows, transposed) with hi/lo split
#pragma unroll
        for (int hq = 0; hq < 2; hq++) {
            float4 w = *(const float4*)&wp[(size_t)(coT + fr) * CC + kc + k0 + hq * 4];
            float xs[4] = {w.x, w.y, w.z, w.w};
#pragma unroll
            for (int jj = 0; jj < 4; jj++) {
                unsigned hb = tf32_bits(xs[jj]);
                float hf = __uint_as_float(hb);
                unsigned lb = tf32_bits(xs[jj] - hf);
                As2[k0 + hq * 4 + jj][fr] = make_float2(hf, __uint_as_float(lb));
            }
        }
        {
            int gi = iT + fr;
            float4 v = (gi < NN)
                ? *(const float4*)&g_val[((size_t)bi * NN + gi) * CC + kc + k0]
                : make_float4(0.f, 0.f, 0.f, 0.f);
            float4 v2 = (gi < NN)
                ? *(const float4*)&g_val[((size_t)bi * NN + gi) * CC + kc + k0 + 4]
                : make_float4(0.f, 0.f, 0.f, 0.f);
            float xs[8] = {v.x, v.y, v.z, v.w, v2.x, v2.y, v2.z, v2.w};
#pragma unroll
            for (int jj = 0; jj < 8; jj++) {
                unsigned hb = tf32_bits(xs[jj]);
                float hf = __uint_as_float(hb);
                unsigned lb = tf32_bits(xs[jj] - hf);
                Bs2[k0 + jj][fr] = make_float2(hf, __uint_as_float(lb));
            }
        }
        __syncthreads();

#pragma unroll
        for (int ks = 0; ks < 2; ks++) {
            int kb = ks * 8;
            unsigned bhi[4][2], blo[4][2];
#pragma unroll
            for (int na = 0; na < 4; na++) {
                int n = wi * 32 + na * 8 + g;
                float2 b0 = Bs2[kb + t4][n];
                float2 b1 = Bs2[kb + t4 + 4][n];
                bhi[na][0] = __float_as_uint(b0.x);
                blo[na][0] = __float_as_uint(b0.y);
                bhi[na][1] = __float_as_uint(b1.x);
                blo[na][1] = __float_as_uint(b1.y);
            }
#pragma unroll
            for (int ma = 0; ma < 4; ma++) {
                int m0 = wc * 64 + ma * 16 + g;
                float2 a0 = As2[kb + t4][m0];
                float2 a1 = As2[kb + t4][m0 + 8];
                float2 a2 = As2[kb + t4 + 4][m0];
                float2 a3 = As2[kb + t4 + 4][m0 + 8];
                unsigned ahi[4] = {__float_as_uint(a0.x), __float_as_uint(a1.x),
                                   __float_as_uint(a2.x), __float_as_uint(a3.x)};
                unsigned alo[4] = {__float_as_uint(a0.y), __float_as_uint(a1.y),
                                   __float_as_uint(a2.y), __float_as_uint(a3.y)};
#pragma unroll
                for (int na = 0; na < 4; na++) {
                    mma_tf32(acc[ma][na], alo, bhi[na]);
                    mma_tf32(acc[ma][na], ahi, blo[na]);
                    mma_tf32(acc[ma][na], ahi, bhi[na]);
                }
            }
        }
        __syncthreads();
    }

    // epilogue: c0:(g,2t), c1:(g,2t+1), c2:(g+8,2t), c3:(g+8,2t+1)
#pragma unroll
    for (int ma = 0; ma < 4; ma++) {
        int co0 = coT + wc * 64 + ma * 16 + g;
        float bz0 = bp[co0], bz1 = bp[co0 + 8];
#pragma unroll
        for (int na = 0; na < 4; na++) {
            int i0 = iT + wi * 32 + na * 8 + 2 * t4;
            if (i0 < NN) {   // i0 even, NN even -> pair valid
                *(float2*)&out[((size_t)bi * CC + co0) * NN + i0] =
                    make_float2(acc[ma][na][0] + bz0, acc[ma][na][1] + bz0);
                *(float2*)&out[((size_t)bi * CC + co0 + 8) * NN + i0] =
                    make_float2(acc[ma][na][2] + bz1, acc[ma][na][3] + bz1);
            }
        }
    }
}

// ---------------- launch ----------------------------------------------------
extern "C" void kernel_launch(void* const* d_in, const int* in_sizes, int n_in,
                              void* d_out, int out_size) {
    const float* queries = (const float*)d_in[0];
    const float* keys    = (const float*)d_in[1];
    const float* values  = (const float*)d_in[2];
    const float* boxes   = (const float*)d_in[3];
    const float* curmask = (const float*)d_in[4];
    const float* wq      = (const float*)d_in[5];
    const float* wk      = (const float*)d_in[6];
    const float* wv      = (const float*)d_in[7];
    const float* w_proj  = (const float*)d_in[8];
    const float* b_proj  = (const float*)d_in[9];
    float* out = (float*)d_out;

    prep_kernel<<<SORT_BLKS + MASK_BLKS + QKV_BLKS, 256>>>(
        boxes, curmask, queries, keys, values, wq, wk, wv);
    attn_kernel<<<dim3((BS * NN + 7) / 8), 256>>>();
    proj_kernel<<<dim3((NN + TIT - 1) / TIT, CC / TCO, BS), 256>>>(w_proj, b_proj, out);
}

// round 11
// speedup vs baseline: 1.2452x; 1.2375x over previous
#include <cuda_runtime.h>
#include <math.h>

#define BS 8
#define CC 256
#define NN 1500
#define HH 8
#define DK 32

// ---------------- scratch (static device globals; no allocs) ----------------
// q/k/v stored head-interleaved: [b][n][h*DK]  (256 floats per token row)
__device__ float g_q[(size_t)BS * NN * CC];
__device__ float g_k[(size_t)BS * NN * CC];
__device__ float g_v[(size_t)BS * NN * CC];
__device__ float g_val[(size_t)BS * NN * CC];              // [b][n][c]
__device__ unsigned short g_nbr[(size_t)BS * NN * NN];     // per-row neighbor j lists
__device__ int g_cnt[BS * NN];
__device__ int g_perm[BS * NN];                            // spatial-sorted order

// ---------------- fused prep: sort (8) + mask (1504) + qkv (1152) -----------
#define SORT_BLKS 8
#define MASK_BLKS (188 * BS)
#define QKV_BLKS  (6 * BS * HH * 3)

__global__ __launch_bounds__(256, 4) void prep_kernel(const float* __restrict__ boxes,
                                                      const float* __restrict__ cm,
                                                      const float* __restrict__ qin,
                                                      const float* __restrict__ kin,
                                                      const float* __restrict__ vin,
                                                      const float* __restrict__ wq,
                                                      const float* __restrict__ wk,
                                                      const float* __restrict__ wv) {
    __shared__ __align__(16) char sbuf[NN * 24];   // 36000 B union
    int blk = blockIdx.x;
    int t = threadIdx.x;

    if (blk < SORT_BLKS) {
        // ----- spatial counting sort, one block per batch -----
        int* hist = (int*)sbuf;
        int* offs = hist + 64;
        int b = blk;
        if (t < 64) hist[t] = 0;
        __syncthreads();
        const float4* bb = (const float4*)(boxes + (size_t)b * NN * 4);
        for (int n = t; n < NN; n += 256) {
            float4 bx = bb[n];
            int kx = min(7, max(0, (int)(bx.x * 8.0f)));
            int ky = min(7, max(0, (int)(bx.y * 8.0f)));
            atomicAdd(&hist[kx * 8 + ky], 1);
        }
        __syncthreads();
        if (t == 0) {
            int run = 0;
            for (int k = 0; k < 64; k++) { offs[k] = run; run += hist[k]; }
        }
        __syncthreads();
        for (int n = t; n < NN; n += 256) {
            float4 bx = bb[n];
            int kx = min(7, max(0, (int)(bx.x * 8.0f)));
            int ky = min(7, max(0, (int)(bx.y * 8.0f)));
            int pos = atomicAdd(&offs[kx * 8 + ky], 1);
            g_perm[b * NN + pos] = n;
        }
        return;
    }

    if (blk < SORT_BLKS + MASK_BLKS) {
        // ----- mask + neighbor list, warp per query (packed smem) -----
        int u = blk - SORT_BLKS;
        int b = u / 188;
        int bx = u % 188;
        float4* sbox = (float4*)sbuf;              // (x1, y1, x2, y2)
        float2* sac = (float2*)(sbuf + NN * 16);   // (area, cm)
        const float4* bb = (const float4*)(boxes + (size_t)b * NN * 4);
        for (int idx = t; idx < NN; idx += 256) {
            float4 bxv = bb[idx];
            float x1 = bxv.x - 0.5f * bxv.z;
            float x2 = bxv.x + 0.5f * bxv.z;
            float y1 = bxv.y - 0.5f * bxv.w;
            float y2 = bxv.y + 0.5f * bxv.w;
            sbox[idx] = make_float4(x1, y1, x2, y2);
            sac[idx] = make_float2((x2 - x1) * (y2 - y1),
                                   cm[(size_t)b * NN + idx]);
        }
        __syncthreads();

        int warp = t >> 5, lane = t & 31;
        int i = bx * 8 + warp;
        if (i >= NN) return;
        float4 bi = sbox[i];
        float2 aci = sac[i];
        unsigned short* out = g_nbr + ((size_t)b * NN + i) * NN;
        int cnt = 0;
        for (int jb = 0; jb < NN; jb += 32) {
            int j = jb + lane;
            bool nbq = false;
            if (j < NN) {
                float4 bj = sbox[j];
                float2 acj = sac[j];
                float ltx = fmaxf(bi.x, bj.x);
                float lty = fmaxf(bi.y, bj.y);
                float rbx = fminf(bi.z, bj.z);
                float rby = fminf(bi.w, bj.w);
                float iw = fmaxf(rbx - ltx, 0.0f);
                float ih = fmaxf(rby - lty, 0.0f);
                float inter = iw * ih;
                float uni = (aci.x + acj.x) - inter;
                float prod = aci.y * acj.y;
                if (prod == 1.0f) {
                    // exact predicate for fl_RN(inter/uni) > 0.5, no divide
                    float i2 = inter + inter;
                    if (i2 > uni * 1.00001f) nbq = true;
                    else if (i2 < uni * 0.99999f) nbq = false;
                    else nbq = ((double)inter >
                                (double)uni * 0.5000000298023223876953125);
                } else {
                    float iou = __fdiv_rn(inter, uni);
                    nbq = (iou * prod) > 0.5f;
                }
            }
            unsigned bal = __ballot_sync(0xffffffffu, nbq);
            int pos = cnt + __popc(bal & ((1u << lane) - 1u));
            if (nbq) out[pos] = (unsigned short)j;
            cnt += __popc(bal);
        }
        if (lane == 0) g_cnt[b * NN + i] = cnt;
        return;
    }

    // ----- qkv head projections (register-lean: output in two 16-d halves) --
    {
        int u = blk - SORT_BLKS - MASK_BLKS;       // [0, 1152)
        int mat = u / (6 * BS * HH);
        int r = u % (6 * BS * HH);
        int bh = r / 6;
        int xc = r % 6;
        int b = bh >> 3, h = bh & 7;
        float4* sw = (float4*)sbuf;                 // 32x32 weights
        const float* W = (mat == 0 ? wq : (mat == 1 ? wk : wv)) + h * DK * DK;
        const float* X = (mat == 0 ? qin : (mat == 1 ? kin : vin));
        float* O = (mat == 0 ? g_q : (mat == 1 ? g_k : g_v));
        sw[t] = ((const float4*)W)[t];
        __syncthreads();

        int i = xc * 256 + t;
        if (i >= NN) return;
        float x[DK];
        const float* xp = X + ((size_t)b * CC + h * DK) * NN + i;
#pragma unroll
        for (int j = 0; j < DK; j++) x[j] = xp[(size_t)j * NN];

        float4* op = (float4*)(O + ((size_t)b * NN + i) * CC + h * DK);
#pragma unroll
        for (int half = 0; half < 2; half++) {
            float outv[16];
#pragma unroll
            for (int d = 0; d < 16; d++) {
                int de = half * 16 + d;
                float acc = 0.0f;
#pragma unroll
                for (int jq = 0; jq < 8; jq++) {
                    float4 w4 = sw[de * 8 + jq];
                    acc = fmaf(w4.x, x[jq * 4 + 0], acc);
                    acc = fmaf(w4.y, x[jq * 4 + 1], acc);
                    acc = fmaf(w4.z, x[jq * 4 + 2], acc);
                    acc = fmaf(w4.w, x[jq * 4 + 3], acc);
                }
                outv[d] = acc;
            }
#pragma unroll
            for (int rr = 0; rr < 4; rr++)
                op[half * 4 + rr] = make_float4(outv[rr * 4], outv[rr * 4 + 1],
                                                outv[rr * 4 + 2], outv[rr * 4 + 3]);
        }
    }
}

// ---------------- sparse masked attention (warp per query, ALL heads) -------
__device__ __forceinline__ void os_update(float& m, float& l, float4& o,
                                          float s, const float4& v) {
    float mn = fmaxf(m, s);
    float sc = __expf(m - mn);
    float p = __expf(s - mn);        // s==-inf (padding) -> p=0
    l = l * sc + p;
    o.x = fmaf(p, v.x, o.x * sc);
    o.y = fmaf(p, v.y, o.y * sc);
    o.z = fmaf(p, v.z, o.z * sc);
    o.w = fmaf(p, v.w, o.w * sc);
    m = mn;
}

__global__ __launch_bounds__(256, 3) void attn_kernel() {
    int warp = threadIdx.x >> 5, lane = threadIdx.x & 31;
    int gs = blockIdx.x * 8 + warp;          // sorted rank within b*NN
    if (gs >= BS * NN) return;
    int b = gs / NN;
    int gi = b * NN + g_perm[gs];            // actual b*NN + i

    int cnt = g_cnt[gi];
    size_t rowq = (size_t)gi * CC;
    int lo = 4 * lane, hi = 128 + 4 * lane;
    const float* kbase = g_k + (size_t)b * NN * CC;
    const float* vbase = g_v + (size_t)b * NN * CC;
    float* valr = g_val + rowq;

    if (cnt == 0) {   // has_nb == 0 fallback: val = v
        const float* vr = g_v + rowq;
        *(float4*)(valr + lo) = *(const float4*)(vr + lo);
        *(float4*)(valr + hi) = *(const float4*)(vr + hi);
        return;
    }

    float4 q0 = *(const float4*)(g_q + rowq + lo);
    float4 q1 = *(const float4*)(g_q + rowq + hi);
    const unsigned short* nb = g_nbr + (size_t)gi * NN;
    int cm1 = cnt - 1;

    float minit = (cnt < NN) ? 0.0f : -INFINITY;
    float m0 = minit, m1 = minit, l0 = 0.f, l1 = 0.f;
    float4 o0 = {0,0,0,0}, o1 = {0,0,0,0};

#define R8(s) s += __shfl_xor_sync(0xffffffffu, s, 1); \
              s += __shfl_xor_sync(0xffffffffu, s, 2); \
              s += __shfl_xor_sync(0xffffffffu, s, 4);

    for (int t = 0; t < cnt; t += 2) {
        int jA = nb[t], jB = nb[min(t + 1, cm1)];
        const float* kA = kbase + (size_t)jA * CC;
        const float* vA = vbase + (size_t)jA * CC;
        const float* kB = kbase + (size_t)jB * CC;
        const float* vB = vbase + (size_t)jB * CC;
        float4 kA0 = *(const float4*)(kA + lo), kA1 = *(const float4*)(kA + hi);
        float4 vA0 = *(const float4*)(vA + lo), vA1 = *(const float4*)(vA + hi);
        float4 kB0 = *(const float4*)(kB + lo), kB1 = *(const float4*)(kB + hi);
        float4 vB0 = *(const float4*)(vB + lo), vB1 = *(const float4*)(vB + hi);

        float sA0 = q0.x * kA0.x + q0.y * kA0.y + q0.z * kA0.z + q0.w * kA0.w;
        float sA1 = q1.x * kA1.x + q1.y * kA1.y + q1.z * kA1.z + q1.w * kA1.w;
        float sB0 = q0.x * kB0.x + q0.y * kB0.y + q0.z * kB0.z + q0.w * kB0.w;
        float sB1 = q1.x * kB1.x + q1.y * kB1.y + q1.z * kB1.z + q1.w * kB1.w;
        R8(sA0) R8(sA1) R8(sB0) R8(sB1)
        if (t + 1 >= cnt) { sB0 = -INFINITY; sB1 = -INFINITY; }

        os_update(m0, l0, o0, sA0, vA0);
        os_update(m0, l0, o0, sB0, vB0);
        os_update(m1, l1, o1, sA1, vA1);
        os_update(m1, l1, o1, sB1, vB1);
    }
#undef R8

    float inv0 = 1.0f / (l0 + 1e-8f);
    float inv1 = 1.0f / (l1 + 1e-8f);
    *(float4*)(valr + lo) = make_float4(o0.x * inv0, o0.y * inv0,
                                        o0.z * inv0, o0.w * inv0);
    *(float4*)(valr + hi) = make_float4(o1.x * inv1, o1.y * inv1,
                                        o1.z * inv1, o1.w * inv1);
}

// ---------------- output projection  out = Wp @ val + b ---------------------
// Scalar FFMA, 128(co) x 64(i) tile, 128 threads, 8x8 per thread, KC=32 with
// register-prefetch double buffering. Measured at the scalar-FFMA roofline.
#define PCO 128
#define PII 64
#define PKC 32
__global__ __launch_bounds__(128) void proj_kernel(const float* __restrict__ wp,
                                                   const float* __restrict__ bp,
                                                   float* __restrict__ out) {
    __shared__ float Ws[PKC][PCO + 4];   // [ci][co]
    __shared__ float Vs[PKC][PII + 4];   // [ci][i]
    int b = blockIdx.z;
    int coT = blockIdx.y * PCO;
    int iT = blockIdx.x * PII;
    int t = threadIdx.x;
    int tx = t & 7;                    // i group: tx*4 and tx*4+32
    int ty = t >> 3;                   // co group (0..15): ty*4 and ty*4+64
    int ci4 = (t & 7) * 4;             // load column group (0..28)
    int r0 = t >> 3;                   // load row base (0..15)

    float4 wpre[8], vpre[4];
#pragma unroll
    for (int p = 0; p < 8; p++)
        wpre[p] = *(const float4*)&wp[(size_t)(coT + r0 + p * 16) * CC + ci4];
#pragma unroll
    for (int p = 0; p < 4; p++) {
        int gi = iT + r0 + p * 16;
        vpre[p] = (gi < NN) ? *(const float4*)&g_val[((size_t)b * NN + gi) * CC + ci4]
                            : make_float4(0.f, 0.f, 0.f, 0.f);
    }

    float acc[8][8] = {};

    for (int kc = 0; kc < CC; kc += PKC) {
#pragma unroll
        for (int p = 0; p < 8; p++) {
            int r = r0 + p * 16;
            Ws[ci4 + 0][r] = wpre[p].x; Ws[ci4 + 1][r] = wpre[p].y;
            Ws[ci4 + 2][r] = wpre[p].z; Ws[ci4 + 3][r] = wpre[p].w;
        }
#pragma unroll
        for (int p = 0; p < 4; p++) {
            int io = r0 + p * 16;
            Vs[ci4 + 0][io] = vpre[p].x; Vs[ci4 + 1][io] = vpre[p].y;
            Vs[ci4 + 2][io] = vpre[p].z; Vs[ci4 + 3][io] = vpre[p].w;
        }
        __syncthreads();

        if (kc + PKC < CC) {
            int kcn = kc + PKC;
#pragma unroll
            for (int p = 0; p < 8; p++)
                wpre[p] = *(const float4*)&wp[(size_t)(coT + r0 + p * 16) * CC + kcn + ci4];
#pragma unroll
            for (int p = 0; p < 4; p++) {
                int gi = iT + r0 + p * 16;
                vpre[p] = (gi < NN) ? *(const float4*)&g_val[((size_t)b * NN + gi) * CC + kcn + ci4]
                                    : make_float4(0.f, 0.f, 0.f, 0.f);
            }
        }

#pragma unroll 8
        for (int ci = 0; ci < PKC; ci++) {
            float4 w0 = *(const float4*)&Ws[ci][ty * 4];
            float4 w1 = *(const float4*)&Ws[ci][64 + ty * 4];
            float4 v0 = *(const float4*)&Vs[ci][tx * 4];
            float4 v1 = *(const float4*)&Vs[ci][32 + tx * 4];
            float wr[8] = {w0.x, w0.y, w0.z, w0.w, w1.x, w1.y, w1.z, w1.w};
            float vr[8] = {v0.x, v0.y, v0.z, v0.w, v1.x, v1.y, v1.z, v1.w};
#pragma unroll
            for (int a = 0; a < 8; a++)
#pragma unroll
                for (int e = 0; e < 8; e++)
                    acc[a][e] = fmaf(wr[a], vr[e], acc[a][e]);
        }
        __syncthreads();
    }

#pragma unroll
    for (int a = 0; a < 8; a++) {
        int co = coT + (a < 4 ? (ty * 4 + a) : (64 + ty * 4 + (a - 4)));
        float bias = bp[co];
#pragma unroll
        for (int half = 0; half < 2; half++) {
            int gi = iT + (half == 0 ? tx * 4 : 32 + tx * 4);
            int e0 = half * 4;
            if (gi < NN) {   // NN % 4 == 0, whole float4 valid
                float4 r = make_float4(acc[a][e0 + 0] + bias, acc[a][e0 + 1] + bias,
                                       acc[a][e0 + 2] + bias, acc[a][e0 + 3] + bias);
                *(float4*)&out[((size_t)b * CC + co) * NN + gi] = r;
            }
        }
    }
}

// ---------------- launch ----------------------------------------------------
extern "C" void kernel_launch(void* const* d_in, const int* in_sizes, int n_in,
                              void* d_out, int out_size) {
    const float* queries = (const float*)d_in[0];
    const float* keys    = (const float*)d_in[1];
    const float* values  = (const float*)d_in[2];
    const float* boxes   = (const float*)d_in[3];
    const float* curmask = (const float*)d_in[4];
    const float* wq      = (const float*)d_in[5];
    const float* wk      = (const float*)d_in[6];
    const float* wv      = (const float*)d_in[7];
    const float* w_proj  = (const float*)d_in[8];
    const float* b_proj  = (const float*)d_in[9];
    float* out = (float*)d_out;

    prep_kernel<<<SORT_BLKS + MASK_BLKS + QKV_BLKS, 256>>>(
        boxes, curmask, queries, keys, values, wq, wk, wv);
    attn_kernel<<<dim3((BS * NN + 7) / 8), 256>>>();
    proj_kernel<<<dim3((NN + PII - 1) / PII, CC / PCO, BS), 128>>>(w_proj, b_proj, out);
}